// round 6
// baseline (speedup 1.0000x reference)
#include <cuda_runtime.h>
#include <math.h>

#define T_LEN    8192
#define NDELAY   360
#define NTHREADS 1024
#define ELEMS    (T_LEN / NTHREADS)      // 8
#define PAD      6784                    // >= 16*420 = 6720 (max lag, K=4)
#define BUF_LEN  (T_LEN + PAD)
#define SKIP_TH  1e-5f
#define ROUND_COST 550.0f

// ---------------------------------------------------------------------------
// y = x/(1+s), s = a1 z^-L1 + a2 z^-L2 (two taps; straight-through one-hot is
// exactly hard in fp32). Squaring ladder:
//   1/(1+s) = (1-s)(1+s^2)(1+s^4)(1+s^8)/(1 - s^16)   (K passes, K<=4)
// Remainder 1/(1-s^{2^K}) deviates from identity by <= rho^{2^K}/(1-..),
// rho = |a1|+|a2|. If rho^{2^K} < 1e-5 (<< 1e-3 tol) the serial chunk phase
// is skipped entirely. A uniform cost model picks K.
// ---------------------------------------------------------------------------

__device__ __forceinline__ float tanh_fast(float x) {
    x = fminf(fmaxf(x, -15.0f), 15.0f);
    float e = __expf(2.0f * x);
    return (e - 1.0f) * __frcp_rn(e + 1.0f);
}

// coefficients of sign * s^N:  term i = sign*C(N,i)*a1^i*a2^(N-i) @ lag i*L1+(N-i)*L2
template <int N>
__device__ __forceinline__ void spow(float a1, float a2, int L1, int L2,
                                     float sign, float* c, int* l) {
#pragma unroll
    for (int i = 0; i <= N; i++) {
        float b = 1.0f;
#pragma unroll
        for (int q = 0; q < i; q++) b = b * (float)(N - q) / (float)(q + 1);
        float t = b;
#pragma unroll
        for (int q = 0; q < i; q++) t *= a1;
#pragma unroll
        for (int q = 0; q < N - i; q++) t *= a2;
        c[i] = sign * t;
        l[i] = i * L1 + (N - i) * L2;
    }
}

template <int NT>
__device__ __forceinline__ float tap_sum(const float* __restrict__ src, int t,
                                         const float* c, const int* l) {
    float v[NT];
#pragma unroll
    for (int j = 0; j < NT; j++) v[j] = src[t - l[j]];
#pragma unroll
    for (int j = 0; j < NT; j++) v[j] *= c[j];
#pragma unroll
    for (int st = 1; st < NT; st *= 2)
#pragma unroll
        for (int j = 0; j + st < NT; j += 2 * st) v[j] += v[j + st];
    return v[0];
}

// FIR pass with register carry. FIRST: init carry from src center.
// store=false on the final pass when no serial phase follows.
template <int NT, bool FIRST>
__device__ __forceinline__ void fir_pass(float r[ELEMS],
                                         const float* __restrict__ src,
                                         float* __restrict__ dst,
                                         const float* c, const int* l,
                                         int tid, bool store) {
#pragma unroll
    for (int i = 0; i < ELEMS; i++) {
        const int t = i * NTHREADS + tid;
        float acc = (FIRST ? src[t] : r[i]) + tap_sum<NT>(src, t, c, l);
        r[i] = acc;
        if (store) dst[t] = acc;
    }
    if (store) __syncthreads();
}

template <int NT>
__device__ __forceinline__ void iir_chunks(float* __restrict__ buf,
                                           const float* c, const int* l,
                                           int W, int tid) {
    for (int s0 = 0; s0 < T_LEN; s0 += W) {
        const int end = (s0 + W < T_LEN) ? (s0 + W) : T_LEN;
        for (int t = s0 + tid; t < end; t += NTHREADS)
            buf[t] += tap_sum<NT>(buf, t, c, l);
        __syncthreads();
    }
}

__global__ void __launch_bounds__(NTHREADS, 1)
ks_fused_kernel(const float* __restrict__ x,
                const float* __restrict__ gumbel,
                const float* __restrict__ delayp,
                const float* __restrict__ fb,
                const float* __restrict__ rc,
                float* __restrict__ out) {
    extern __shared__ float smem[];
    float* bufA = smem;
    float* bufB = smem + BUF_LEN;
    float* A = bufA + PAD;
    float* B = bufB + PAD;

    __shared__ float s_rv[32];
    __shared__ int   s_ri[32];
    __shared__ int   s_m;
    __shared__ float s_a1, s_a2;

    const int tid  = threadIdx.x;
    const int row  = blockIdx.x;
    const int lane = tid & 31;
    const int wid  = tid >> 5;

    // --- staging loads first (hide DRAM latency under setup) ---
    const float4* x4 = (const float4*)(x + (size_t)row * T_LEN);
    float4 stg[ELEMS / 4];
#pragma unroll
    for (int i = 0; i < ELEMS / 4; i++) stg[i] = x4[tid + i * NTHREADS];

    // --- thread 0: scalar coefficients ---
    if (tid == 0) {
        float k1 = tanh_fast(tanh_fast(rc[0]));
        float k2 = tanh_fast(tanh_fast(rc[1]));
        float a1 = k1 * (1.0f - k2);
        float a2 = fminf(fmaxf(k2, -0.999f), 0.999f);
        float bound = 0.999f - fabsf(a2);
        a1 = fminf(fmaxf(a1, -bound), bound);
        float sg = __frcp_rn(1.0f + __expf(-fb[0]));
        float g  = __powf(sg, 0.45f);
        s_a1 = a1 * g;
        s_a2 = a2 * g;
    }

    // --- zero pads ---
#pragma unroll
    for (int i = 0; i < (PAD + NTHREADS - 1) / NTHREADS; i++) {
        const int p = i * NTHREADS + tid;
        if (p < PAD) { bufA[p] = 0.0f; bufB[p] = 0.0f; }
    }

    // --- argmax over 360 logits (first-index tie-break) ---
    float lv = -INFINITY;
    int   li = tid;
    if (tid < NDELAY) lv = delayp[tid] + gumbel[tid];
#pragma unroll
    for (int off = 16; off > 0; off >>= 1) {
        float ov = __shfl_down_sync(0xffffffffu, lv, off);
        int   oi = __shfl_down_sync(0xffffffffu, li, off);
        if (ov > lv || (ov == lv && oi < li)) { lv = ov; li = oi; }
    }
    if (lane == 0) { s_rv[wid] = lv; s_ri[wid] = li; }
    __syncthreads();
    if (wid == 0) {
        lv = s_rv[lane];
        li = s_ri[lane];
#pragma unroll
        for (int off = 16; off > 0; off >>= 1) {
            float ov = __shfl_down_sync(0xffffffffu, lv, off);
            int   oi = __shfl_down_sync(0xffffffffu, li, off);
            if (ov > lv || (ov == lv && oi < li)) { lv = ov; li = oi; }
        }
        if (lane == 0) s_m = li;
    }

    // --- commit staged x to SMEM ---
    {
        float4* a4 = (float4*)A;
#pragma unroll
        for (int i = 0; i < ELEMS / 4; i++) a4[tid + i * NTHREADS] = stg[i];
    }
    __syncthreads();

    const float a1 = s_a1;
    const float a2 = s_a2;
    const int   m  = s_m;
    const int   L1 = 61 + m;
    const int   L2 = 61 + ((m + 1) % NDELAY);
    const int   C  = (L1 < L2) ? L1 : L2;

    const float rho   = fabsf(a1) + fabsf(a2);
    const float rho2  = rho * rho;
    const float rho4  = rho2 * rho2;
    const float rho8  = rho4 * rho4;
    const float rho16 = rho8 * rho8;
    const float rp[5] = { rho, rho2, rho4, rho8, rho16 };

    // --- uniform cost model: pick K in 1..4 ---
    int bestK = 1;
    {
        float passCum = 0.0f, best = 1e30f;
#pragma unroll
        for (int k = 1; k <= 4; k++) {
            passCum += (float)((1 << (k - 1)) + 2) * 256.0f + ROUND_COST;
            float cost = passCum;
            if (rp[k] >= SKIP_TH) {
                const int W   = C << k;
                const int nch = (T_LEN + W - 1) / W;
                cost += (float)((1 << k) + 2) * 256.0f + ROUND_COST * (float)nch;
            }
            if (cost < best) { best = cost; bestK = k; }
        }
    }
    const bool chunks = (rp[bestK] >= SKIP_TH);

    // --- FIR ladder with register carry, ping-ponging A/B ---
    float r[ELEMS];
    float* cur = B;   // result buffer after pass 1
    {
        float c[2]; int l[2];
        spow<1>(a1, a2, L1, L2, -1.0f, c, l);
        fir_pass<2, true>(r, A, B, c, l, tid, (bestK > 1) || chunks);
    }
    if (bestK >= 2) {
        float c[3]; int l[3];
        spow<2>(a1, a2, L1, L2, 1.0f, c, l);
        fir_pass<3, false>(r, B, A, c, l, tid, (bestK > 2) || chunks);
        cur = A;
    }
    if (bestK >= 3) {
        float c[5]; int l[5];
        spow<4>(a1, a2, L1, L2, 1.0f, c, l);
        fir_pass<5, false>(r, A, B, c, l, tid, (bestK > 3) || chunks);
        cur = B;
    }
    if (bestK >= 4) {
        float c[9]; int l[9];
        spow<8>(a1, a2, L1, L2, 1.0f, c, l);
        fir_pass<9, false>(r, B, A, c, l, tid, chunks);
        cur = A;
    }

    if (chunks) {
        // serial remainder: y += s^{2^K} y, chunk width 2^K * C
        if (bestK == 1) {
            float c[3]; int l[3];
            spow<2>(a1, a2, L1, L2, 1.0f, c, l);
            iir_chunks<3>(cur, c, l, C << 1, tid);
        } else if (bestK == 2) {
            float c[5]; int l[5];
            spow<4>(a1, a2, L1, L2, 1.0f, c, l);
            iir_chunks<5>(cur, c, l, C << 2, tid);
        } else if (bestK == 3) {
            float c[9]; int l[9];
            spow<8>(a1, a2, L1, L2, 1.0f, c, l);
            iir_chunks<9>(cur, c, l, C << 3, tid);
        } else {
            float c[17]; int l[17];
            spow<16>(a1, a2, L1, L2, 1.0f, c, l);
            iir_chunks<17>(cur, c, l, C << 4, tid);
        }
        // vectorized writeback from smem
        float4* o4 = (float4*)(out + (size_t)row * T_LEN);
        const float4* r4 = (const float4*)cur;
#pragma unroll
        for (int i = 0; i < ELEMS / 4; i++)
            o4[tid + i * NTHREADS] = r4[tid + i * NTHREADS];
    } else {
        // result lives in registers; write out directly (coalesced scalar)
        float* o = out + (size_t)row * T_LEN;
#pragma unroll
        for (int i = 0; i < ELEMS; i++)
            o[i * NTHREADS + tid] = r[i];
    }
}

// ---------------------------------------------------------------------------
// inputs: excitation[128*8192] f32, gumbel[360], delay_param[360],
//         feedback_gain[1], reflection_coeffs[2]; output f32 [128*8192]
// ---------------------------------------------------------------------------
extern "C" void kernel_launch(void* const* d_in, const int* in_sizes, int n_in,
                              void* d_out, int out_size) {
    const float* x      = (const float*)d_in[0];
    const float* gumbel = (const float*)d_in[1];
    const float* delayp = (const float*)d_in[2];
    const float* fb     = (const float*)d_in[3];
    const float* rc     = (const float*)d_in[4];
    float* out = (float*)d_out;

    const int rows = in_sizes[0] / T_LEN;
    const int smem_bytes = 2 * BUF_LEN * sizeof(float);

    cudaFuncSetAttribute(ks_fused_kernel,
                         cudaFuncAttributeMaxDynamicSharedMemorySize, smem_bytes);
    ks_fused_kernel<<<rows, NTHREADS, smem_bytes>>>(x, gumbel, delayp, fb, rc, out);
}